// round 7
// baseline (speedup 1.0000x reference)
#include <cuda_runtime.h>

// ---------------------------------------------------------------------------
// CrossVariableAttention: fused LN + QKV GEMM + 4x4 cross-head attention +
// proj GEMM + residual.  fp32, fma.rn.f32x2 row-pair accumulators,
// 2 CTAs/SM (TM=16, smem 84.6KB, <=128 regs).
//
// B=4, L=8, C=256, S=64, W=64 -> N = 131072 rows, 256 channels.
// element [row n, chan c] at outer*C*4096 + c*4096 + inner.
// ---------------------------------------------------------------------------

#define TM 16

// shared memory layout (float offsets)
#define X_S        0            // raw x          [16][261]
#define X_STRIDE   261
#define XN2        4176         // xnorm^T / y^T  [256][18] (row-pairs adjacent)
#define XN_STRIDE  18
#define QKV        8784         // qkv / out [16][773];  BS aliased at same base
#define QKV_STRIDE 773
#define BS         8784         // weight slices (aliased into QKV region)
#define SMEM_FLOATS 21152       // 84608 bytes

__device__ float g_wqkv_t[768 * 256];   // [k][j] transposed qkv weight
__device__ float g_wproj_t[256 * 256];  // [k][c] transposed proj weight

__global__ void transpose_w_kernel(const float* __restrict__ wqkv,
                                   const float* __restrict__ wproj) {
    int idx = blockIdx.x * blockDim.x + threadIdx.x;
    if (idx < 768 * 256) {
        int j = idx >> 8, k = idx & 255;
        g_wqkv_t[k * 768 + j] = wqkv[idx];
    }
    if (idx < 256 * 256) {
        int j = idx >> 8, k = idx & 255;
        g_wproj_t[k * 256 + j] = wproj[idx];
    }
}

typedef unsigned long long ull;

__device__ __forceinline__ ull pack2(float v) {
    ull r;
    asm("mov.b64 %0, {%1, %1};" : "=l"(r) : "r"(__float_as_uint(v)));
    return r;
}
__device__ __forceinline__ void fma2(ull& d, ull a, ull b) {
    asm("fma.rn.f32x2 %0, %1, %2, %0;" : "+l"(d) : "l"(a), "l"(b));
}
__device__ __forceinline__ void unpack2(ull v, float& lo, float& hi) {
    unsigned int l, h;
    asm("mov.b64 {%0, %1}, %2;" : "=r"(l), "=r"(h) : "l"(v));
    lo = __uint_as_float(l);
    hi = __uint_as_float(h);
}

__global__ __launch_bounds__(256, 2)
void cva_kernel(const float* __restrict__ x, const float* __restrict__ bproj,
                const float* __restrict__ gamma, const float* __restrict__ beta,
                float* __restrict__ out)
{
    extern __shared__ float sm[];
    const int t = threadIdx.x;
    const int rg = t & 1;          // row half: rows rg*8 .. rg*8+7
    const int cg = t >> 1;         // col group (0..127)
    const long long n0 = (long long)blockIdx.x * TM;
    const long long outer = n0 >> 12;
    const int inner = (int)(n0 & 4095);
    const float* xg = x + outer * (256LL * 4096LL) + inner;
    float* og = out + outer * (256LL * 4096LL) + inner;

    // ---- Phase A: load x tile ----
    #pragma unroll
    for (int i = 0; i < 16; i++) {
        int idx = i * 256 + t;
        int c = idx >> 4, r = idx & 15;
        sm[X_S + r * X_STRIDE + c] = xg[(long long)c * 4096 + r];
    }
    __syncthreads();

    // ---- Phase B: LayerNorm (16 lanes per row) -> xn^T [k][row] ----
    {
        int r = t >> 4;            // 0..15
        int sub = t & 15;
        const float* xr = &sm[X_S + r * X_STRIDE];
        float s = 0.f, s2 = 0.f;
        #pragma unroll
        for (int i = 0; i < 16; i++) {
            float v = xr[sub + 16 * i];
            s += v; s2 += v * v;
        }
        #pragma unroll
        for (int m = 1; m < 16; m <<= 1) {
            s  += __shfl_xor_sync(0xffffffffu, s,  m);
            s2 += __shfl_xor_sync(0xffffffffu, s2, m);
        }
        float mean = s * (1.f / 256.f);
        float var  = fmaf(-mean, mean, s2 * (1.f / 256.f));
        float rstd = rsqrtf(var + 1e-5f);
        #pragma unroll
        for (int i = 0; i < 16; i++) {
            int k = sub + 16 * i;
            float v = (xr[k] - mean) * rstd * __ldg(&gamma[k]) + __ldg(&beta[k]);
            sm[XN2 + k * XN_STRIDE + r] = v;
        }
    }

    // ---- Phase C: GEMM1  qkv[r][j] = sum_k xn[r][k]*wqkv_t[k][j] ----
    // thread: rows rg*8..+7 (4 row-pairs), cols cg*6..+5.  24 FFMA2/k-step.
    ull acc[4][6];
    #pragma unroll
    for (int p = 0; p < 4; p++)
        #pragma unroll
        for (int c = 0; c < 6; c++) acc[p][c] = 0ull;

    float4 pw[6];
    #pragma unroll
    for (int i = 0; i < 6; i++) pw[i] = *(const float4*)&g_wqkv_t[t * 4 + i * 1024];
    #pragma unroll
    for (int i = 0; i < 6; i++) ((float4*)&sm[BS])[t + i * 256] = pw[i];
    #pragma unroll
    for (int i = 0; i < 6; i++)
        pw[i] = *(const float4*)&g_wqkv_t[6144 + t * 4 + i * 1024];
    __syncthreads();

    #pragma unroll 1
    for (int s = 0; s < 32; s++) {
        const float* xb = &sm[XN2 + s * (8 * XN_STRIDE) + rg * 8];
        const float* bb = &sm[BS + (s & 1) * 6144 + cg * 6];
        #pragma unroll
        for (int kk = 0; kk < 8; kk++) {
            const ull* ar = (const ull*)(xb + kk * XN_STRIDE);
            ull A0 = ar[0], A1 = ar[1], A2 = ar[2], A3 = ar[3];
            const float* bp = bb + kk * 768;
            ull B0 = pack2(bp[0]), B1 = pack2(bp[1]), B2 = pack2(bp[2]);
            ull B3 = pack2(bp[3]), B4 = pack2(bp[4]), B5 = pack2(bp[5]);
            fma2(acc[0][0], A0, B0); fma2(acc[0][1], A0, B1);
            fma2(acc[0][2], A0, B2); fma2(acc[0][3], A0, B3);
            fma2(acc[0][4], A0, B4); fma2(acc[0][5], A0, B5);
            fma2(acc[1][0], A1, B0); fma2(acc[1][1], A1, B1);
            fma2(acc[1][2], A1, B2); fma2(acc[1][3], A1, B3);
            fma2(acc[1][4], A1, B4); fma2(acc[1][5], A1, B5);
            fma2(acc[2][0], A2, B0); fma2(acc[2][1], A2, B1);
            fma2(acc[2][2], A2, B2); fma2(acc[2][3], A2, B3);
            fma2(acc[2][4], A2, B4); fma2(acc[2][5], A2, B5);
            fma2(acc[3][0], A3, B0); fma2(acc[3][1], A3, B1);
            fma2(acc[3][2], A3, B2); fma2(acc[3][3], A3, B3);
            fma2(acc[3][4], A3, B4); fma2(acc[3][5], A3, B5);
        }
        if (s + 1 < 32) {
            #pragma unroll
            for (int i = 0; i < 6; i++)
                ((float4*)&sm[BS + ((s + 1) & 1) * 6144])[t + i * 256] = pw[i];
            if (s + 2 < 32) {
                #pragma unroll
                for (int i = 0; i < 6; i++)
                    pw[i] = *(const float4*)&g_wqkv_t[(s + 2) * 6144 + t * 4 + i * 1024];
            }
        }
        __syncthreads();
    }
    // write qkv tile (BS now dead; same region, post-sync)
    #pragma unroll
    for (int p = 0; p < 4; p++) {
        int row = rg * 8 + 2 * p;
        #pragma unroll
        for (int c = 0; c < 6; c++) {
            float lo, hi;
            unpack2(acc[p][c], lo, hi);
            sm[QKV + row * QKV_STRIDE + cg * 6 + c] = lo;
            sm[QKV + (row + 1) * QKV_STRIDE + cg * 6 + c] = hi;
        }
    }
    __syncthreads();

    // ---- Phase D: per-row 4x4 cross-head attention ----
    // q[h][d]=qkv[12d+3h], k=+1, v=+2;  y[4d+h] = sum_g attn[h][g] v[g][d]
    {
        int r = t >> 4;
        int sub = t & 15;          // lane handles d = i*16+sub, i<4
        const float* qk = &sm[QKV + r * QKV_STRIDE];
        float lg[16];
        #pragma unroll
        for (int i = 0; i < 16; i++) lg[i] = 0.f;
        #pragma unroll
        for (int i = 0; i < 4; i++) {
            const float* p = qk + 12 * (i * 16 + sub);
            float q0 = p[0], k0v = p[1];
            float q1 = p[3], k1v = p[4];
            float q2 = p[6], k2v = p[7];
            float q3 = p[9], k3v = p[10];
            lg[0]  = fmaf(q0, k0v, lg[0]);  lg[1]  = fmaf(q0, k1v, lg[1]);
            lg[2]  = fmaf(q0, k2v, lg[2]);  lg[3]  = fmaf(q0, k3v, lg[3]);
            lg[4]  = fmaf(q1, k0v, lg[4]);  lg[5]  = fmaf(q1, k1v, lg[5]);
            lg[6]  = fmaf(q1, k2v, lg[6]);  lg[7]  = fmaf(q1, k3v, lg[7]);
            lg[8]  = fmaf(q2, k0v, lg[8]);  lg[9]  = fmaf(q2, k1v, lg[9]);
            lg[10] = fmaf(q2, k2v, lg[10]); lg[11] = fmaf(q2, k3v, lg[11]);
            lg[12] = fmaf(q3, k0v, lg[12]); lg[13] = fmaf(q3, k1v, lg[13]);
            lg[14] = fmaf(q3, k2v, lg[14]); lg[15] = fmaf(q3, k3v, lg[15]);
        }
        #pragma unroll
        for (int m = 1; m < 16; m <<= 1) {
            #pragma unroll
            for (int i = 0; i < 16; i++)
                lg[i] += __shfl_xor_sync(0xffffffffu, lg[i], m);
        }
        float attn[16];
        #pragma unroll
        for (int h = 0; h < 4; h++) {
            float a0 = lg[h * 4 + 0] * 0.125f, a1 = lg[h * 4 + 1] * 0.125f;
            float a2 = lg[h * 4 + 2] * 0.125f, a3 = lg[h * 4 + 3] * 0.125f;
            float mx = fmaxf(fmaxf(a0, a1), fmaxf(a2, a3));
            float e0 = expf(a0 - mx), e1 = expf(a1 - mx);
            float e2 = expf(a2 - mx), e3 = expf(a3 - mx);
            float inv = 1.f / (e0 + e1 + e2 + e3);
            attn[h * 4 + 0] = e0 * inv; attn[h * 4 + 1] = e1 * inv;
            attn[h * 4 + 2] = e2 * inv; attn[h * 4 + 3] = e3 * inv;
        }
        #pragma unroll
        for (int i = 0; i < 4; i++) {
            int d = i * 16 + sub;
            const float* p = qk + 12 * d;
            float v0 = p[2], v1 = p[5], v2 = p[8], v3 = p[11];
            #pragma unroll
            for (int h = 0; h < 4; h++) {
                float y = attn[h * 4 + 0] * v0 + attn[h * 4 + 1] * v1 +
                          attn[h * 4 + 2] * v2 + attn[h * 4 + 3] * v3;
                sm[XN2 + (4 * d + h) * XN_STRIDE + r] = y;   // y^T
            }
        }
    }
    __syncthreads();

    // ---- Phase E: GEMM2  out[r][c] = x + sum_k y[r][k]*wproj_t[k][c] + bp ----
    // thread: 4 row-pairs, cols cg*2..+1.  8 FFMA2/k-step.
    ull acc2[4][2];
    #pragma unroll
    for (int p = 0; p < 4; p++) { acc2[p][0] = 0ull; acc2[p][1] = 0ull; }

    float4 pv[2];
    #pragma unroll
    for (int i = 0; i < 2; i++) pv[i] = *(const float4*)&g_wproj_t[t * 4 + i * 1024];
    #pragma unroll
    for (int i = 0; i < 2; i++) ((float4*)&sm[BS])[t + i * 256] = pv[i];
    #pragma unroll
    for (int i = 0; i < 2; i++)
        pv[i] = *(const float4*)&g_wproj_t[2048 + t * 4 + i * 1024];
    __syncthreads();

    #pragma unroll 1
    for (int s = 0; s < 32; s++) {
        const float* xb = &sm[XN2 + s * (8 * XN_STRIDE) + rg * 8];
        const float* bb = &sm[BS + (s & 1) * 2048 + cg * 2];
        #pragma unroll
        for (int kk = 0; kk < 8; kk++) {
            const ull* ar = (const ull*)(xb + kk * XN_STRIDE);
            ull A0 = ar[0], A1 = ar[1], A2 = ar[2], A3 = ar[3];
            const float* bp = bb + kk * 256;
            ull B0 = pack2(bp[0]), B1 = pack2(bp[1]);
            fma2(acc2[0][0], A0, B0); fma2(acc2[0][1], A0, B1);
            fma2(acc2[1][0], A1, B0); fma2(acc2[1][1], A1, B1);
            fma2(acc2[2][0], A2, B0); fma2(acc2[2][1], A2, B1);
            fma2(acc2[3][0], A3, B0); fma2(acc2[3][1], A3, B1);
        }
        if (s + 1 < 32) {
            #pragma unroll
            for (int i = 0; i < 2; i++)
                ((float4*)&sm[BS + ((s + 1) & 1) * 2048])[t + i * 256] = pv[i];
            if (s + 2 < 32) {
                #pragma unroll
                for (int i = 0; i < 2; i++)
                    pv[i] = *(const float4*)&g_wproj_t[(s + 2) * 2048 + t * 4 + i * 1024];
            }
        }
        __syncthreads();
    }

    // epilogue: residual + bias, park result in QKV region (BS dead)
    {
        float bp0 = __ldg(&bproj[cg * 2 + 0]);
        float bp1 = __ldg(&bproj[cg * 2 + 1]);
        #pragma unroll
        for (int p = 0; p < 4; p++) {
            int row = rg * 8 + 2 * p;
            float lo, hi;
            unpack2(acc2[p][0], lo, hi);
            sm[QKV + row * QKV_STRIDE + cg * 2] =
                lo + sm[X_S + row * X_STRIDE + cg * 2] + bp0;
            sm[QKV + (row + 1) * QKV_STRIDE + cg * 2] =
                hi + sm[X_S + (row + 1) * X_STRIDE + cg * 2] + bp0;
            unpack2(acc2[p][1], lo, hi);
            sm[QKV + row * QKV_STRIDE + cg * 2 + 1] =
                lo + sm[X_S + row * X_STRIDE + cg * 2 + 1] + bp1;
            sm[QKV + (row + 1) * QKV_STRIDE + cg * 2 + 1] =
                hi + sm[X_S + (row + 1) * X_STRIDE + cg * 2 + 1] + bp1;
        }
    }
    __syncthreads();

    // ---- Phase F: coalesced store ----
    #pragma unroll
    for (int i = 0; i < 16; i++) {
        int idx = i * 256 + t;
        int c = idx >> 4, r = idx & 15;
        og[(long long)c * 4096 + r] = sm[QKV + r * QKV_STRIDE + c];
    }
}

extern "C" void kernel_launch(void* const* d_in, const int* in_sizes, int n_in,
                              void* d_out, int out_size)
{
    const float* x     = (const float*)d_in[0];
    const float* wqkv  = (const float*)d_in[1];
    const float* wproj = (const float*)d_in[2];
    const float* bproj = (const float*)d_in[3];
    const float* gamma = (const float*)d_in[4];
    const float* beta  = (const float*)d_in[5];
    float* out = (float*)d_out;

    transpose_w_kernel<<<(768 * 256 + 255) / 256, 256>>>(wqkv, wproj);

    const size_t shmem = SMEM_FLOATS * sizeof(float);   // 84608 B
    cudaFuncSetAttribute(cva_kernel, cudaFuncAttributeMaxDynamicSharedMemorySize,
                         (int)shmem);
    cva_kernel<<<8192, 256, shmem>>>(x, bproj, gamma, beta, out);
}